// round 2
// baseline (speedup 1.0000x reference)
#include <cuda_runtime.h>
#include <cstdint>

#define MARGIN   0.3f
#define NEG_FILL 1e9f

#define TI 64      // i-tile
#define TJ 64      // j-tile
#define TK 32      // k-chunk
#define JSPLIT 4   // j-dimension splits for occupancy

#define MAXB 8192

// Scratch (allocation-free rule: __device__ globals)
__device__ float g_sq[MAXB];
__device__ int   g_hp[MAXB];   // float bits, running max of hardest-positive dist (init -1.0f)
__device__ int   g_hn[MAXB];   // float bits, running min of hardest-negative dist (init 1e9f)
__device__ float g_total;
__device__ float g_count;

__global__ void init_kernel(int B) {
    int i = blockIdx.x * blockDim.x + threadIdx.x;
    if (i < B) {
        g_hp[i] = __float_as_int(-1.0f);
        g_hn[i] = __float_as_int(NEG_FILL);
    }
    if (i == 0) { g_total = 0.0f; g_count = 0.0f; }
}

// one warp per row: squared L2 norm
__global__ void norms_kernel(const float* __restrict__ E, int B, int D) {
    int warp = (blockIdx.x * blockDim.x + threadIdx.x) >> 5;
    int lane = threadIdx.x & 31;
    if (warp >= B) return;
    const float* row = E + (size_t)warp * D;
    float s = 0.0f;
    for (int k = lane; k < D; k += 32) { float v = row[k]; s = fmaf(v, v, s); }
    #pragma unroll
    for (int o = 16; o > 0; o >>= 1) s += __shfl_xor_sync(0xffffffffu, s, o);
    if (lane == 0) g_sq[warp] = s;
}

// Main: tiled Gram + fused masked max/min epilogue.
// grid: (B/TI, JSPLIT), block: 256 threads (16x16 logical), 4x4 micro-tile.
__global__ void __launch_bounds__(256, 2)
triplet_main_kernel(const float* __restrict__ E,
                    const int* __restrict__ L,      // labels are int32 (jax default, no x64)
                    int B, int D)
{
    __shared__ float As[TK][TI + 4];   // +4 pad: keeps 16B alignment, breaks conflicts
    __shared__ float Bs[TK][TJ + 4];
    __shared__ float sqj_s[TJ];
    __shared__ int   lj_s[TJ];

    const int tid = threadIdx.x;
    const int tx = tid & 15;           // j direction
    const int ty = tid >> 4;           // i direction

    const int i0 = blockIdx.x * TI;
    const int jtiles_total = B / TJ;
    const int jt_per_split = jtiles_total / JSPLIT;
    const int jt_begin = blockIdx.y * jt_per_split;
    const int jt_end   = jt_begin + jt_per_split;

    // per-thread anchor rows: i0 + ty*4 + a
    float sqi[4];
    int li[4];
    #pragma unroll
    for (int a = 0; a < 4; a++) {
        int i = i0 + ty * 4 + a;
        sqi[a] = g_sq[i];
        li[a]  = L[i];
    }

    float hp[4], hn[4];
    #pragma unroll
    for (int a = 0; a < 4; a++) { hp[a] = -1.0f; hn[a] = NEG_FILL; }

    for (int jt = jt_begin; jt < jt_end; jt++) {
        const int j0 = jt * TJ;
        __syncthreads();   // protect lj_s/sqj_s from previous iteration's epilogue readers

        if (tid < TJ) {
            sqj_s[tid] = g_sq[j0 + tid];
            lj_s[tid]  = L[j0 + tid];
        }

        float acc[4][4];
        #pragma unroll
        for (int a = 0; a < 4; a++)
            #pragma unroll
            for (int b = 0; b < 4; b++) acc[a][b] = 0.0f;

        for (int kc = 0; kc < D; kc += TK) {
            // load A tile (TI x TK) transposed -> As[k][i], coalesced on k
            #pragma unroll
            for (int s = 0; s < (TI * TK) / 256; s++) {
                int idx = tid + s * 256;
                int i = idx >> 5;          // /TK
                int k = idx & 31;          // %TK
                As[k][i] = E[(size_t)(i0 + i) * D + kc + k];
            }
            #pragma unroll
            for (int s = 0; s < (TJ * TK) / 256; s++) {
                int idx = tid + s * 256;
                int j = idx >> 5;
                int k = idx & 31;
                Bs[k][j] = E[(size_t)(j0 + j) * D + kc + k];
            }
            __syncthreads();

            #pragma unroll
            for (int k = 0; k < TK; k++) {
                float4 av = *(const float4*)&As[k][ty * 4];
                float4 bv = *(const float4*)&Bs[k][tx * 4];
                float ar[4] = {av.x, av.y, av.z, av.w};
                float br[4] = {bv.x, bv.y, bv.z, bv.w};
                #pragma unroll
                for (int a = 0; a < 4; a++)
                    #pragma unroll
                    for (int b = 0; b < 4; b++)
                        acc[a][b] = fmaf(ar[a], br[b], acc[a][b]);
            }
            __syncthreads();
        }

        // epilogue: distance + masked running max/min
        #pragma unroll
        for (int a = 0; a < 4; a++) {
            const int i = i0 + ty * 4 + a;
            #pragma unroll
            for (int b = 0; b < 4; b++) {
                const int jl = tx * 4 + b;
                const int j = j0 + jl;
                float d2 = sqi[a] + sqj_s[jl] - 2.0f * acc[a][b];
                float d = sqrtf(fmaxf(d2, 0.0f));
                bool same = (li[a] == lj_s[jl]);
                if (same) {
                    if (j != i) hp[a] = fmaxf(hp[a], d);
                } else {
                    hn[a] = fminf(hn[a], d);
                }
            }
        }
    }

    // reduce across the 16 tx lanes sharing the same anchor rows.
    // lanes with equal ty are 16 consecutive lanes within a warp -> xor shuffle works.
    #pragma unroll
    for (int a = 0; a < 4; a++) {
        #pragma unroll
        for (int o = 8; o > 0; o >>= 1) {
            hp[a] = fmaxf(hp[a], __shfl_xor_sync(0xffffffffu, hp[a], o));
            hn[a] = fminf(hn[a], __shfl_xor_sync(0xffffffffu, hn[a], o));
        }
    }
    if (tx == 0) {
        #pragma unroll
        for (int a = 0; a < 4; a++) {
            int i = i0 + ty * 4 + a;
            // all candidates >= 0; fills are -1.0f (hp) / 1e9f (hn):
            // int-bit compare is order-preserving here.
            atomicMax(&g_hp[i], __float_as_int(hp[a]));
            atomicMin(&g_hn[i], __float_as_int(hn[a]));
        }
    }
}

__global__ void finalize_kernel(int B) {
    __shared__ float s_tot[8];
    __shared__ float s_cnt[8];
    int i = blockIdx.x * blockDim.x + threadIdx.x;
    float per = 0.0f, cnt = 0.0f;
    if (i < B) {
        float hp = __int_as_float(g_hp[i]);
        float hn = __int_as_float(g_hn[i]);
        bool valid = (hp >= 0.0f) && (hn < NEG_FILL);
        if (valid) {
            per = fmaxf(hp - hn + MARGIN, 0.0f);
            cnt = 1.0f;
        }
    }
    #pragma unroll
    for (int o = 16; o > 0; o >>= 1) {
        per += __shfl_xor_sync(0xffffffffu, per, o);
        cnt += __shfl_xor_sync(0xffffffffu, cnt, o);
    }
    int warp = threadIdx.x >> 5, lane = threadIdx.x & 31;
    if (lane == 0) { s_tot[warp] = per; s_cnt[warp] = cnt; }
    __syncthreads();
    if (warp == 0) {
        per = (lane < (blockDim.x >> 5)) ? s_tot[lane] : 0.0f;
        cnt = (lane < (blockDim.x >> 5)) ? s_cnt[lane] : 0.0f;
        #pragma unroll
        for (int o = 4; o > 0; o >>= 1) {
            per += __shfl_xor_sync(0xffffffffu, per, o);
            cnt += __shfl_xor_sync(0xffffffffu, cnt, o);
        }
        if (lane == 0) {
            atomicAdd(&g_total, per);
            atomicAdd(&g_count, cnt);
        }
    }
}

__global__ void writeout_kernel(float* out) {
    float t = g_total, c = g_count;
    out[0] = (c > 0.0f) ? (t / fmaxf(c, 1.0f)) : 0.0f;
}

extern "C" void kernel_launch(void* const* d_in, const int* in_sizes, int n_in,
                              void* d_out, int out_size)
{
    const float* E = (const float*)d_in[0];
    const int* L = (const int*)d_in[1];
    const int B = in_sizes[1];
    const int D = in_sizes[0] / B;
    float* out = (float*)d_out;

    init_kernel<<<(B + 255) / 256, 256>>>(B);
    {
        int threads = 256;
        int blocks = (B * 32 + threads - 1) / threads;
        norms_kernel<<<blocks, threads>>>(E, B, D);
    }
    {
        dim3 grid(B / TI, JSPLIT);
        triplet_main_kernel<<<grid, 256>>>(E, L, B, D);
    }
    finalize_kernel<<<(B + 255) / 256, 256>>>(B);
    writeout_kernel<<<1, 1>>>(out);
}

// round 3
// speedup vs baseline: 2.7638x; 2.7638x over previous
#include <cuda_runtime.h>
#include <cuda_bf16.h>
#include <cstdint>

#define MARGIN   0.3f
#define NEG_FILL 1e9f

#define MAXB 8192
#define MAXE (4096 * 256)

// ---- device scratch (allocation-free rule) ----
__device__ __nv_bfloat16 g_hi[MAXE];
__device__ __nv_bfloat16 g_lo[MAXE];
__device__ float g_sq[MAXB];
__device__ int   g_hp[MAXB];   // float bits, running max hardest-positive (init -1.0f)
__device__ int   g_hn[MAXB];   // float bits, running min hardest-negative (init 1e9f)
__device__ float g_total;
__device__ float g_count;

__global__ void init_kernel(int B) {
    int i = blockIdx.x * blockDim.x + threadIdx.x;
    if (i < B) {
        g_hp[i] = __float_as_int(-1.0f);
        g_hn[i] = __float_as_int(NEG_FILL);
    }
    if (i == 0) { g_total = 0.0f; g_count = 0.0f; }
}

// split fp32 -> hi/lo bf16 pair
__global__ void split_kernel(const float* __restrict__ E, int n) {
    int i = blockIdx.x * blockDim.x + threadIdx.x;
    if (i < n) {
        float x = E[i];
        __nv_bfloat16 h = __float2bfloat16(x);
        float r = x - __bfloat162float(h);
        g_hi[i] = h;
        g_lo[i] = __float2bfloat16(r);
    }
}

// one warp per row: exact fp32 squared L2 norm
__global__ void norms_kernel(const float* __restrict__ E, int B, int D) {
    int warp = (blockIdx.x * blockDim.x + threadIdx.x) >> 5;
    int lane = threadIdx.x & 31;
    if (warp >= B) return;
    const float* row = E + (size_t)warp * D;
    float s = 0.0f;
    for (int k = lane; k < D; k += 32) { float v = row[k]; s = fmaf(v, v, s); }
    #pragma unroll
    for (int o = 16; o > 0; o >>= 1) s += __shfl_xor_sync(0xffffffffu, s, o);
    if (lane == 0) g_sq[warp] = s;
}

// ---- tensor-core main kernel ----
#define TM 128
#define TN 128
#define KC 32            // K elements per smem chunk
#define KSTRIDE 40       // padded smem row stride (elems): 80B, 16B-aligned, bank-clean

__device__ __forceinline__ void mma_bf16(float c[4], const unsigned a[4], const unsigned b[2]) {
    asm volatile(
        "mma.sync.aligned.m16n8k16.row.col.f32.bf16.bf16.f32 "
        "{%0,%1,%2,%3}, {%4,%5,%6,%7}, {%8,%9}, {%0,%1,%2,%3};\n"
        : "+f"(c[0]), "+f"(c[1]), "+f"(c[2]), "+f"(c[3])
        : "r"(a[0]), "r"(a[1]), "r"(a[2]), "r"(a[3]), "r"(b[0]), "r"(b[1]));
}

__global__ void __launch_bounds__(256)
triplet_mma_kernel(const int* __restrict__ L, int B, int D)
{
    __shared__ __nv_bfloat16 sAhi[TM * KSTRIDE];
    __shared__ __nv_bfloat16 sAlo[TM * KSTRIDE];
    __shared__ __nv_bfloat16 sBhi[TN * KSTRIDE];
    __shared__ __nv_bfloat16 sBlo[TN * KSTRIDE];
    __shared__ int s_hp[TM];
    __shared__ int s_hn[TM];

    const int tid = threadIdx.x;
    const int w   = tid >> 5;
    const int wr  = w >> 2;          // warp row 0..1 (64 rows each)
    const int wc  = w & 3;           // warp col 0..3 (32 cols each)
    const int lane = tid & 31;
    const int gid = lane >> 2;       // group id 0..7
    const int tig = lane & 3;        // thread-in-group 0..3

    const int i0 = blockIdx.x * TM;
    const int j0 = blockIdx.y * TN;

    if (tid < TM) {
        s_hp[tid] = __float_as_int(-1.0f);
        s_hn[tid] = __float_as_int(NEG_FILL);
    }

    float c[4][4][4];
    #pragma unroll
    for (int mf = 0; mf < 4; mf++)
        #pragma unroll
        for (int nf = 0; nf < 4; nf++)
            #pragma unroll
            for (int r = 0; r < 4; r++) c[mf][nf][r] = 0.0f;

    for (int kc = 0; kc < D; kc += KC) {
        // fill 4 tiles: 512 uint4 units each, 2 per thread
        #pragma unroll
        for (int s = 0; s < 2; s++) {
            int u = tid + s * 256;
            int row = u >> 2;
            int kb  = (u & 3) * 8;
            size_t gOffA = (size_t)(i0 + row) * D + kc + kb;
            size_t gOffB = (size_t)(j0 + row) * D + kc + kb;
            int sOff = row * KSTRIDE + kb;
            *(uint4*)&sAhi[sOff] = *(const uint4*)&g_hi[gOffA];
            *(uint4*)&sAlo[sOff] = *(const uint4*)&g_lo[gOffA];
            *(uint4*)&sBhi[sOff] = *(const uint4*)&g_hi[gOffB];
            *(uint4*)&sBlo[sOff] = *(const uint4*)&g_lo[gOffB];
        }
        __syncthreads();

        #pragma unroll
        for (int ks = 0; ks < KC / 16; ks++) {
            // B fragments for this warp (hi and lo)
            unsigned bh[4][2], bl[4][2];
            #pragma unroll
            for (int nf = 0; nf < 4; nf++) {
                int n = wc * 32 + nf * 8 + gid;
                int off = n * KSTRIDE + ks * 16 + tig * 2;
                bh[nf][0] = *(const unsigned*)&sBhi[off];
                bh[nf][1] = *(const unsigned*)&sBhi[off + 8];
                bl[nf][0] = *(const unsigned*)&sBlo[off];
                bl[nf][1] = *(const unsigned*)&sBlo[off + 8];
            }
            #pragma unroll
            for (int mf = 0; mf < 4; mf++) {
                int r = wr * 64 + mf * 16 + gid;
                int off0 = r * KSTRIDE + ks * 16 + tig * 2;
                int off1 = off0 + 8 * KSTRIDE;
                unsigned ah[4], al[4];
                ah[0] = *(const unsigned*)&sAhi[off0];
                ah[1] = *(const unsigned*)&sAhi[off1];
                ah[2] = *(const unsigned*)&sAhi[off0 + 8];
                ah[3] = *(const unsigned*)&sAhi[off1 + 8];
                al[0] = *(const unsigned*)&sAlo[off0];
                al[1] = *(const unsigned*)&sAlo[off1];
                al[2] = *(const unsigned*)&sAlo[off0 + 8];
                al[3] = *(const unsigned*)&sAlo[off1 + 8];
                #pragma unroll
                for (int nf = 0; nf < 4; nf++) {
                    mma_bf16(c[mf][nf], ah, bh[nf]);   // hi*hi
                    mma_bf16(c[mf][nf], ah, bl[nf]);   // hi*lo
                    mma_bf16(c[mf][nf], al, bh[nf]);   // lo*hi
                }
            }
        }
        __syncthreads();
    }

    // ---- fused epilogue: distance + masked max/min ----
    float hp[4][2], hn[4][2];
    #pragma unroll
    for (int mf = 0; mf < 4; mf++) {
        hp[mf][0] = hp[mf][1] = -1.0f;
        hn[mf][0] = hn[mf][1] = NEG_FILL;
    }

    #pragma unroll
    for (int mf = 0; mf < 4; mf++) {
        #pragma unroll
        for (int ro = 0; ro < 2; ro++) {
            int ig = i0 + wr * 64 + mf * 16 + gid + ro * 8;
            float si = g_sq[ig];
            int   lii = L[ig];
            #pragma unroll
            for (int nf = 0; nf < 4; nf++) {
                #pragma unroll
                for (int co = 0; co < 2; co++) {
                    int jg = j0 + wc * 32 + nf * 8 + tig * 2 + co;
                    float dot = c[mf][nf][ro * 2 + co];
                    float d2 = si + g_sq[jg] - 2.0f * dot;
                    float d = sqrtf(fmaxf(d2, 0.0f));
                    bool same = (lii == L[jg]);
                    if (same) {
                        if (jg != ig) hp[mf][ro] = fmaxf(hp[mf][ro], d);
                    } else {
                        hn[mf][ro] = fminf(hn[mf][ro], d);
                    }
                }
            }
        }
    }

    // reduce across tig (lanes sharing the same rows): xor 1, 2
    #pragma unroll
    for (int mf = 0; mf < 4; mf++)
        #pragma unroll
        for (int ro = 0; ro < 2; ro++) {
            #pragma unroll
            for (int o = 1; o <= 2; o <<= 1) {
                hp[mf][ro] = fmaxf(hp[mf][ro], __shfl_xor_sync(0xffffffffu, hp[mf][ro], o));
                hn[mf][ro] = fminf(hn[mf][ro], __shfl_xor_sync(0xffffffffu, hn[mf][ro], o));
            }
        }

    // smem atomics merge across warps (tig==0 lanes only)
    if (tig == 0) {
        #pragma unroll
        for (int mf = 0; mf < 4; mf++)
            #pragma unroll
            for (int ro = 0; ro < 2; ro++) {
                int rloc = wr * 64 + mf * 16 + gid + ro * 8;
                atomicMax(&s_hp[rloc], __float_as_int(hp[mf][ro]));
                atomicMin(&s_hn[rloc], __float_as_int(hn[mf][ro]));
            }
    }
    __syncthreads();

    // one global atomic per row per CTA (bit-pattern ordered: all values >= -1)
    if (tid < TM) {
        int row = i0 + tid;
        atomicMax(&g_hp[row], s_hp[tid]);
        atomicMin(&g_hn[row], s_hn[tid]);
    }
}

__global__ void finalize_kernel(int B) {
    __shared__ float s_tot[8];
    __shared__ float s_cnt[8];
    int i = blockIdx.x * blockDim.x + threadIdx.x;
    float per = 0.0f, cnt = 0.0f;
    if (i < B) {
        float hp = __int_as_float(g_hp[i]);
        float hn = __int_as_float(g_hn[i]);
        bool valid = (hp >= 0.0f) && (hn < NEG_FILL);
        if (valid) {
            per = fmaxf(hp - hn + MARGIN, 0.0f);
            cnt = 1.0f;
        }
    }
    #pragma unroll
    for (int o = 16; o > 0; o >>= 1) {
        per += __shfl_xor_sync(0xffffffffu, per, o);
        cnt += __shfl_xor_sync(0xffffffffu, cnt, o);
    }
    int warp = threadIdx.x >> 5, lane = threadIdx.x & 31;
    if (lane == 0) { s_tot[warp] = per; s_cnt[warp] = cnt; }
    __syncthreads();
    if (warp == 0) {
        per = (lane < (blockDim.x >> 5)) ? s_tot[lane] : 0.0f;
        cnt = (lane < (blockDim.x >> 5)) ? s_cnt[lane] : 0.0f;
        #pragma unroll
        for (int o = 4; o > 0; o >>= 1) {
            per += __shfl_xor_sync(0xffffffffu, per, o);
            cnt += __shfl_xor_sync(0xffffffffu, cnt, o);
        }
        if (lane == 0) {
            atomicAdd(&g_total, per);
            atomicAdd(&g_count, cnt);
        }
    }
}

__global__ void writeout_kernel(float* out) {
    float t = g_total, c = g_count;
    out[0] = (c > 0.0f) ? (t / fmaxf(c, 1.0f)) : 0.0f;
}

extern "C" void kernel_launch(void* const* d_in, const int* in_sizes, int n_in,
                              void* d_out, int out_size)
{
    const float* E = (const float*)d_in[0];
    const int* L = (const int*)d_in[1];
    const int B = in_sizes[1];
    const int D = in_sizes[0] / B;
    float* out = (float*)d_out;

    init_kernel<<<(B + 255) / 256, 256>>>(B);
    split_kernel<<<(B * D + 255) / 256, 256>>>(E, B * D);
    {
        int threads = 256;
        int blocks = (B * 32 + threads - 1) / threads;
        norms_kernel<<<blocks, threads>>>(E, B, D);
    }
    {
        dim3 grid(B / TM, B / TN);
        triplet_mma_kernel<<<grid, 256>>>(L, B, D);
    }
    finalize_kernel<<<(B + 255) / 256, 256>>>(B);
    writeout_kernel<<<1, 1>>>(out);
}

// round 4
// speedup vs baseline: 5.2728x; 1.9078x over previous
#include <cuda_runtime.h>
#include <cuda_bf16.h>
#include <cstdint>

#define MARGIN   0.3f
#define NEG_FILL 1e9f
#define MAXB 8192
#define MAXE (4096 * 256)

#define TM 128
#define TN 128
#define KC 32
#define KST 40      // smem row stride in elems (80B): 16B-aligned, ldmatrix conflict-free

// ---- device scratch (allocation-free rule) ----
__device__ __nv_bfloat16 g_hi[MAXE];
__device__ __nv_bfloat16 g_lo[MAXE];
__device__ float g_sq[MAXB];
__device__ int   g_hp[MAXB];
__device__ int   g_hn[MAXB];

// ---------------- prep: split + norms + init, one block per row ----------------
__global__ void prep_kernel(const float* __restrict__ E, int B, int D) {
    int row = blockIdx.x;
    int t = threadIdx.x;
    float s = 0.0f;
    for (int k = t; k < D; k += blockDim.x) {
        float x = E[(size_t)row * D + k];
        __nv_bfloat16 h = __float2bfloat16(x);
        float r = x - __bfloat162float(h);
        g_hi[(size_t)row * D + k] = h;
        g_lo[(size_t)row * D + k] = __float2bfloat16(r);
        s = fmaf(x, x, s);
    }
    __shared__ float sm[8];
    #pragma unroll
    for (int o = 16; o > 0; o >>= 1) s += __shfl_xor_sync(0xffffffffu, s, o);
    int w = t >> 5, l = t & 31;
    if (l == 0) sm[w] = s;
    __syncthreads();
    if (t == 0) {
        float tot = 0.0f;
        int nw = blockDim.x >> 5;
        for (int i = 0; i < nw; i++) tot += sm[i];
        g_sq[row] = tot;
        g_hp[row] = __float_as_int(-1.0f);
        g_hn[row] = __float_as_int(NEG_FILL);
    }
}

// ---------------- main: symmetric tiled MMA + fused epilogue ----------------
__device__ __forceinline__ void cp16(void* s, const void* g) {
    unsigned a = (unsigned)__cvta_generic_to_shared(s);
    asm volatile("cp.async.cg.shared.global [%0], [%1], 16;\n" :: "r"(a), "l"(g));
}
__device__ __forceinline__ void cp_commit() { asm volatile("cp.async.commit_group;\n"); }

__device__ __forceinline__ void ldsm4(unsigned r[4], const __nv_bfloat16* p) {
    unsigned a = (unsigned)__cvta_generic_to_shared(p);
    asm volatile("ldmatrix.sync.aligned.m8n8.x4.shared.b16 {%0,%1,%2,%3}, [%4];"
                 : "=r"(r[0]), "=r"(r[1]), "=r"(r[2]), "=r"(r[3]) : "r"(a));
}
__device__ __forceinline__ void mma_bf16(float c[4], const unsigned a[4], const unsigned* b) {
    asm volatile(
        "mma.sync.aligned.m16n8k16.row.col.f32.bf16.bf16.f32 "
        "{%0,%1,%2,%3}, {%4,%5,%6,%7}, {%8,%9}, {%0,%1,%2,%3};\n"
        : "+f"(c[0]), "+f"(c[1]), "+f"(c[2]), "+f"(c[3])
        : "r"(a[0]), "r"(a[1]), "r"(a[2]), "r"(a[3]), "r"(b[0]), "r"(b[1]));
}

extern __shared__ __nv_bfloat16 dynsmem[];

__global__ void __launch_bounds__(256, 2)
triplet_mma_sym(const int* __restrict__ L, int B, int D, int nt)
{
    const int tid = threadIdx.x;
    const int lane = tid & 31;
    const int w = tid >> 5;
    const int wr = w >> 2, wc = w & 3;
    const int gid = lane >> 2, tig = lane & 3;

    // decode upper-triangular (bi <= bj) tile pair from linear block id
    int u = blockIdx.x;
    float ntf = (float)nt + 0.5f;
    int bi = (int)(ntf - sqrtf(fmaxf(ntf * ntf - 2.0f * (float)u, 0.0f)));
    while (bi > 0 && (bi * nt - bi * (bi - 1) / 2) > u) bi--;
    while (((bi + 1) * nt - (bi + 1) * bi / 2) <= u) bi++;
    int bj = bi + (u - (bi * nt - bi * (bi - 1) / 2));
    const int i0 = bi * TM, j0 = bj * TN;

    const int TILE = TM * KST;

    __shared__ int s_hpi[TM], s_hni[TM], s_hpj[TN], s_hnj[TN];
    if (tid < TM) { s_hpi[tid] = __float_as_int(-1.0f); s_hni[tid] = __float_as_int(NEG_FILL); }
    if (tid < TN) { s_hpj[tid] = __float_as_int(-1.0f); s_hnj[tid] = __float_as_int(NEG_FILL); }

    float c[4][4][4];
    #pragma unroll
    for (int mf = 0; mf < 4; mf++)
        #pragma unroll
        for (int nf = 0; nf < 4; nf++)
            #pragma unroll
            for (int r = 0; r < 4; r++) c[mf][nf][r] = 0.0f;

    const int NK = D / KC;

    auto issue = [&](int kc, int s) {
        __nv_bfloat16* b = dynsmem + s * 4 * TILE;
        #pragma unroll
        for (int q = 0; q < 2; q++) {
            int uu = tid + q * 256;
            int row = uu >> 2;
            int kb = (uu & 3) * 8;
            size_t gA = (size_t)(i0 + row) * D + kc * KC + kb;
            size_t gB = (size_t)(j0 + row) * D + kc * KC + kb;
            int so = row * KST + kb;
            cp16(&b[so], &g_hi[gA]);
            cp16(&b[TILE + so], &g_lo[gA]);
            cp16(&b[2 * TILE + so], &g_hi[gB]);
            cp16(&b[3 * TILE + so], &g_lo[gB]);
        }
        cp_commit();
    };

    issue(0, 0);

    const int q8 = lane >> 3, r8 = lane & 7;   // ldmatrix lane decomposition

    for (int kc = 0; kc < NK; kc++) {
        int cur = kc & 1;
        if (kc + 1 < NK) {
            issue(kc + 1, cur ^ 1);
            asm volatile("cp.async.wait_group 1;\n");
        } else {
            asm volatile("cp.async.wait_group 0;\n");
        }
        __syncthreads();

        __nv_bfloat16* sAhi = dynsmem + cur * 4 * TILE;
        __nv_bfloat16* sAlo = sAhi + TILE;
        __nv_bfloat16* sBhi = sAhi + 2 * TILE;
        __nv_bfloat16* sBlo = sAhi + 3 * TILE;

        #pragma unroll
        for (int ks = 0; ks < KC / 16; ks++) {
            // B fragments via ldmatrix.x4 (2 nf groups per load)
            unsigned bh[4][2], bl[4][2];
            #pragma unroll
            for (int h = 0; h < 2; h++) {
                int brow = wc * 32 + (2 * h + (q8 >> 1)) * 8 + r8;
                int bcol = ks * 16 + (q8 & 1) * 8;
                unsigned rh[4], rl[4];
                ldsm4(rh, &sBhi[brow * KST + bcol]);
                ldsm4(rl, &sBlo[brow * KST + bcol]);
                bh[2 * h][0] = rh[0]; bh[2 * h][1] = rh[1];
                bh[2 * h + 1][0] = rh[2]; bh[2 * h + 1][1] = rh[3];
                bl[2 * h][0] = rl[0]; bl[2 * h][1] = rl[1];
                bl[2 * h + 1][0] = rl[2]; bl[2 * h + 1][1] = rl[3];
            }
            #pragma unroll
            for (int mf = 0; mf < 4; mf++) {
                int arow = wr * 64 + mf * 16 + (q8 & 1) * 8 + r8;
                int acol = ks * 16 + (q8 >> 1) * 8;
                unsigned ah[4], al[4];
                ldsm4(ah, &sAhi[arow * KST + acol]);
                ldsm4(al, &sAlo[arow * KST + acol]);
                #pragma unroll
                for (int nf = 0; nf < 4; nf++) {
                    mma_bf16(c[mf][nf], ah, bh[nf]);   // hi*hi
                    mma_bf16(c[mf][nf], ah, bl[nf]);   // hi*lo
                    mma_bf16(c[mf][nf], al, bh[nf]);   // lo*hi
                }
            }
        }
        __syncthreads();
    }

    // ---- fused epilogue, both anchor sides ----
    float sqi[4][2]; int li[4][2];
    float sqj[4][2]; int lj[4][2];
    #pragma unroll
    for (int mf = 0; mf < 4; mf++)
        #pragma unroll
        for (int ro = 0; ro < 2; ro++) {
            int ig = i0 + wr * 64 + mf * 16 + gid + ro * 8;
            sqi[mf][ro] = g_sq[ig];
            li[mf][ro]  = L[ig];
        }
    #pragma unroll
    for (int nf = 0; nf < 4; nf++)
        #pragma unroll
        for (int co = 0; co < 2; co++) {
            int jg = j0 + wc * 32 + nf * 8 + tig * 2 + co;
            sqj[nf][co] = g_sq[jg];
            lj[nf][co]  = L[jg];
        }

    float hpi[4][2], hni[4][2], hpj[4][2], hnj[4][2];
    #pragma unroll
    for (int x = 0; x < 4; x++)
        #pragma unroll
        for (int y = 0; y < 2; y++) {
            hpi[x][y] = -1.0f; hni[x][y] = NEG_FILL;
            hpj[x][y] = -1.0f; hnj[x][y] = NEG_FILL;
        }

    #pragma unroll
    for (int mf = 0; mf < 4; mf++)
        #pragma unroll
        for (int ro = 0; ro < 2; ro++) {
            int ig = i0 + wr * 64 + mf * 16 + gid + ro * 8;
            #pragma unroll
            for (int nf = 0; nf < 4; nf++)
                #pragma unroll
                for (int co = 0; co < 2; co++) {
                    int jg = j0 + wc * 32 + nf * 8 + tig * 2 + co;
                    float dot = c[mf][nf][ro * 2 + co];
                    float d2 = sqi[mf][ro] + sqj[nf][co] - 2.0f * dot;
                    float d = sqrtf(fmaxf(d2, 0.0f));
                    bool same = (li[mf][ro] == lj[nf][co]);
                    bool diag = (ig == jg);
                    if (same) {
                        if (!diag) {
                            hpi[mf][ro] = fmaxf(hpi[mf][ro], d);
                            hpj[nf][co] = fmaxf(hpj[nf][co], d);
                        }
                    } else {
                        hni[mf][ro] = fminf(hni[mf][ro], d);
                        hnj[nf][co] = fminf(hnj[nf][co], d);
                    }
                }
        }

    // i-side: reduce across tig lanes (same rows)
    #pragma unroll
    for (int mf = 0; mf < 4; mf++)
        #pragma unroll
        for (int ro = 0; ro < 2; ro++) {
            #pragma unroll
            for (int o = 1; o <= 2; o <<= 1) {
                hpi[mf][ro] = fmaxf(hpi[mf][ro], __shfl_xor_sync(0xffffffffu, hpi[mf][ro], o));
                hni[mf][ro] = fminf(hni[mf][ro], __shfl_xor_sync(0xffffffffu, hni[mf][ro], o));
            }
        }
    if (tig == 0) {
        #pragma unroll
        for (int mf = 0; mf < 4; mf++)
            #pragma unroll
            for (int ro = 0; ro < 2; ro++) {
                int rl = wr * 64 + mf * 16 + gid + ro * 8;
                atomicMax(&s_hpi[rl], __float_as_int(hpi[mf][ro]));
                atomicMin(&s_hni[rl], __float_as_int(hni[mf][ro]));
            }
    }

    // j-side: reduce across gid lanes (same cols)
    #pragma unroll
    for (int nf = 0; nf < 4; nf++)
        #pragma unroll
        for (int co = 0; co < 2; co++) {
            #pragma unroll
            for (int o = 4; o <= 16; o <<= 1) {
                hpj[nf][co] = fmaxf(hpj[nf][co], __shfl_xor_sync(0xffffffffu, hpj[nf][co], o));
                hnj[nf][co] = fminf(hnj[nf][co], __shfl_xor_sync(0xffffffffu, hnj[nf][co], o));
            }
        }
    if (gid == 0) {
        #pragma unroll
        for (int nf = 0; nf < 4; nf++)
            #pragma unroll
            for (int co = 0; co < 2; co++) {
                int cl = wc * 32 + nf * 8 + tig * 2 + co;
                atomicMax(&s_hpj[cl], __float_as_int(hpj[nf][co]));
                atomicMin(&s_hnj[cl], __float_as_int(hnj[nf][co]));
            }
    }
    __syncthreads();

    // global merge (bit-pattern ordered: all values >= -1.0f)
    if (tid < TM) {
        atomicMax(&g_hp[i0 + tid], s_hpi[tid]);
        atomicMin(&g_hn[i0 + tid], s_hni[tid]);
    }
    if (tid < TN) {
        atomicMax(&g_hp[j0 + tid], s_hpj[tid]);
        atomicMin(&g_hn[j0 + tid], s_hnj[tid]);
    }
}

// ---------------- finalize: single block ----------------
__global__ void finalize1(float* __restrict__ out, int B) {
    __shared__ float st[32], sc[32];
    int t = threadIdx.x;
    float per = 0.0f, cnt = 0.0f;
    for (int i = t; i < B; i += blockDim.x) {
        float hp = __int_as_float(g_hp[i]);
        float hn = __int_as_float(g_hn[i]);
        if (hp >= 0.0f && hn < NEG_FILL) {
            per += fmaxf(hp - hn + MARGIN, 0.0f);
            cnt += 1.0f;
        }
    }
    #pragma unroll
    for (int o = 16; o > 0; o >>= 1) {
        per += __shfl_xor_sync(0xffffffffu, per, o);
        cnt += __shfl_xor_sync(0xffffffffu, cnt, o);
    }
    int w = t >> 5, l = t & 31;
    if (l == 0) { st[w] = per; sc[w] = cnt; }
    __syncthreads();
    if (w == 0) {
        int nw = blockDim.x >> 5;
        per = (l < nw) ? st[l] : 0.0f;
        cnt = (l < nw) ? sc[l] : 0.0f;
        #pragma unroll
        for (int o = 16; o > 0; o >>= 1) {
            per += __shfl_xor_sync(0xffffffffu, per, o);
            cnt += __shfl_xor_sync(0xffffffffu, cnt, o);
        }
        if (l == 0) out[0] = (cnt > 0.0f) ? (per / fmaxf(cnt, 1.0f)) : 0.0f;
    }
}

extern "C" void kernel_launch(void* const* d_in, const int* in_sizes, int n_in,
                              void* d_out, int out_size)
{
    const float* E = (const float*)d_in[0];
    const int* L = (const int*)d_in[1];
    const int B = in_sizes[1];
    const int D = in_sizes[0] / B;
    float* out = (float*)d_out;

    prep_kernel<<<B, 256>>>(E, B, D);

    int nt = B / TM;
    int nblk = nt * (nt + 1) / 2;
    int smembytes = 2 * 4 * TM * KST * (int)sizeof(__nv_bfloat16);  // 81920
    cudaFuncSetAttribute(triplet_mma_sym,
                         cudaFuncAttributeMaxDynamicSharedMemorySize, smembytes);
    triplet_mma_sym<<<nblk, 256, smembytes>>>(L, B, D, nt);

    finalize1<<<1, 1024>>>(out, B);
}